// round 3
// baseline (speedup 1.0000x reference)
#include <cuda_runtime.h>
#include <math.h>

#define RD     2048
#define RE     8
#define RNE    16          // gate(8) + noise(8) output columns
#define RNTOK  16384       // B*S = 8*2048
#define TPB    256
#define NWARPS 8
#define NBLK   128
#define JOBS_PER_WARP 4    // 128 blk * 8 warps * 4 jobs * 4 tokens = 16384
#define NSTEP  (RD / 128)  // 16 d-chunks per dot product
#define PROBS_ELEMS (RNTOK*RE)   // 131072

// packed 2xfp32 FMA (Blackwell sm_100a) — 2x fp32 throughput vs 3-reg FFMA
__device__ __forceinline__ void ffma2(unsigned long long& d,
                                      unsigned long long a,
                                      unsigned long long b) {
    asm("fma.rn.f32x2 %0, %1, %2, %0;" : "+l"(d) : "l"(a), "l"(b));
}

__device__ __forceinline__ float lo32(unsigned long long v) {
    return __uint_as_float((unsigned)(v & 0xffffffffull));
}
__device__ __forceinline__ float hi32(unsigned long long v) {
    return __uint_as_float((unsigned)(v >> 32));
}

__global__ void __launch_bounds__(TPB, 1) router_kernel(
    const float* __restrict__ x,
    const float* __restrict__ gate_w,
    const float* __restrict__ gate_b,
    const float* __restrict__ noise_w,
    const float* __restrict__ noise_b,
    const float* __restrict__ noise,
    float* __restrict__ out, int out_size)
{
    // Weights transposed into smem, expert-major: sw[e][d], e<8 gate, e>=8 noise.
    extern __shared__ float sw[];   // 16 * 2048 floats = 128 KB
    for (int i = threadIdx.x; i < RD * RE; i += TPB) {
        int d = i >> 3, e = i & 7;          // gate_w / noise_w are [D, E] row-major
        sw[e * RD + d]       = gate_w[i];
        sw[(e + 8) * RD + d] = noise_w[i];
    }
    __syncthreads();

    const int lane = threadIdx.x & 31;
    const int warp = threadIdx.x >> 5;
    const int gwarp = blockIdx.x * NWARPS + warp;   // 0..1023

    for (int it = 0; it < JOBS_PER_WARP; ++it) {
        const int group = gwarp + it * (NBLK * NWARPS);  // 0..4095
        const int t0 = group * 4;                        // 4 tokens per warp job

        // acc2[t][e]: packed fp32x2 accumulator
        unsigned long long acc2[4][16];
        #pragma unroll
        for (int t = 0; t < 4; ++t)
            #pragma unroll
            for (int e = 0; e < 16; ++e) acc2[t][e] = 0ull;

        // lane l covers d = s*128 + l*4 .. +3  (NSTEP steps x 128 d)
        const float* xbase = x + (size_t)t0 * RD + lane * 4;

        ulonglong2 xv[4];
        #pragma unroll
        for (int t = 0; t < 4; ++t)
            xv[t] = *reinterpret_cast<const ulonglong2*>(xbase + (size_t)t * RD);

        #pragma unroll 1
        for (int s = 0; s < NSTEP; ++s) {
            // prefetch next d-chunk (wraps to chunk 0 on last iter: dead value,
            // always-valid address) while computing current (MLP=4)
            const int snext = (s + 1) & (NSTEP - 1);
            const float* xnext = xbase + snext * 128;
            ulonglong2 xn[4];
            #pragma unroll
            for (int t = 0; t < 4; ++t)
                xn[t] = *reinterpret_cast<const ulonglong2*>(xnext + (size_t)t * RD);

            const float* swp = sw + s * 128 + lane * 4;
            #pragma unroll
            for (int e = 0; e < 16; ++e) {
                const ulonglong2 wv =
                    *reinterpret_cast<const ulonglong2*>(swp + e * RD);
                #pragma unroll
                for (int t = 0; t < 4; ++t) {
                    ffma2(acc2[t][e], xv[t].x, wv.x);
                    ffma2(acc2[t][e], xv[t].y, wv.y);
                }
            }
            #pragma unroll
            for (int t = 0; t < 4; ++t) xv[t] = xn[t];
        }

        // collapse packed halves, then warp all-reduce (butterfly)
        float acc[4][16];
        #pragma unroll
        for (int t = 0; t < 4; ++t)
            #pragma unroll
            for (int e = 0; e < 16; ++e)
                acc[t][e] = lo32(acc2[t][e]) + hi32(acc2[t][e]);

        #pragma unroll
        for (int m = 16; m >= 1; m >>= 1) {
            #pragma unroll
            for (int t = 0; t < 4; ++t)
                #pragma unroll
                for (int e = 0; e < 16; ++e)
                    acc[t][e] += __shfl_xor_sync(0xffffffffu, acc[t][e], m);
        }

        // lanes 0..3 each finalize one token (all lanes hold full sums)
        if (lane < 4) {
            float my[16];
            #pragma unroll
            for (int t = 0; t < 4; ++t)
                if (lane == t)
                    #pragma unroll
                    for (int e = 0; e < 16; ++e) my[e] = acc[t][e];

            const int tok = t0 + lane;
            float noisy[8];
            #pragma unroll
            for (int e = 0; e < 8; ++e) {
                float lg = my[e]     + gate_b[e];
                float z  = my[e + 8] + noise_b[e];
                // softplus, numerically stable
                float sp = fmaxf(z, 0.f) + log1pf(expf(-fabsf(z)));
                noisy[e] = lg + noise[(size_t)tok * 8 + e] * sp;
            }

            // top-2, tie-break toward lower index (matches lax.top_k)
            float v0 = -INFINITY, v1 = -INFINITY;
            int   i0 = 0,         i1 = 0;
            #pragma unroll
            for (int e = 0; e < 8; ++e) {
                float v = noisy[e];
                if (v > v0)      { v1 = v0; i1 = i0; v0 = v; i0 = e; }
                else if (v > v1) { v1 = v;  i1 = e; }
            }

            // softmax over {v0, v1}; all other experts -> 0
            float e1  = expf(v1 - v0);
            float inv = 1.f / (1.f + e1);
            float p0 = inv, p1 = e1 * inv;

            float pv[8];
            #pragma unroll
            for (int e = 0; e < 8; ++e)
                pv[e] = (e == i0) ? p0 : ((e == i1) ? p1 : 0.f);

            float4* po = reinterpret_cast<float4*>(out + (size_t)tok * 8);
            po[0] = make_float4(pv[0], pv[1], pv[2], pv[3]);
            po[1] = make_float4(pv[4], pv[5], pv[6], pv[7]);

            const int ib = PROBS_ELEMS + tok * 2;
            if (ib + 1 < out_size) {
                out[ib]     = (float)i0;
                out[ib + 1] = (float)i1;
            }
        }
    }
}

extern "C" void kernel_launch(void* const* d_in, const int* in_sizes, int n_in,
                              void* d_out, int out_size) {
    const float* x       = (const float*)d_in[0];
    const float* gate_w  = (const float*)d_in[1];
    const float* gate_b  = (const float*)d_in[2];
    const float* noise_w = (const float*)d_in[3];
    const float* noise_b = (const float*)d_in[4];
    const float* noise   = (const float*)d_in[5];
    // d_in[6] = top_k (fixed = 2, baked into the kernel)

    const size_t smem = (size_t)RNE * RD * sizeof(float);   // 128 KB
    cudaFuncSetAttribute(router_kernel,
                         cudaFuncAttributeMaxDynamicSharedMemorySize, (int)smem);
    router_kernel<<<NBLK, TPB, smem>>>(x, gate_w, gate_b, noise_w, noise_b,
                                       noise, (float*)d_out, out_size);
}

// round 4
// speedup vs baseline: 1.2789x; 1.2789x over previous
#include <cuda_runtime.h>
#include <math.h>

#define RD      2048
#define RE      8
#define RNE     16            // gate(8) + noise(8) expert rows in smem
#define RNTOK   16384         // B*S
#define TPB     512
#define NWARPS  16
#define NBLK    148
#define TOTAL_JOBS (RNTOK/4)  // 4096 jobs of 4 tokens
#define WSTRIDE (NBLK*NWARPS) // 2368 global warps
#define NCHUNK  (RD/32)       // 64 chunks of 32 d
#define PROBS_ELEMS (RNTOK*RE)

// packed 2xfp32 FMA (Blackwell) — 2x fp32 throughput vs 3-reg FFMA
__device__ __forceinline__ void ffma2(unsigned long long& d,
                                      unsigned long long a,
                                      unsigned long long b) {
    asm("fma.rn.f32x2 %0, %1, %2, %0;" : "+l"(d) : "l"(a), "l"(b));
}
__device__ __forceinline__ float lo32(unsigned long long v) {
    return __uint_as_float((unsigned)(v & 0xffffffffull));
}
__device__ __forceinline__ float hi32(unsigned long long v) {
    return __uint_as_float((unsigned)(v >> 32));
}

__global__ void __launch_bounds__(TPB, 1) router_kernel(
    const float* __restrict__ x,
    const float* __restrict__ gate_w,
    const float* __restrict__ gate_b,
    const float* __restrict__ noise_w,
    const float* __restrict__ noise_b,
    const float* __restrict__ noise,
    float* __restrict__ out, int out_size)
{
    // Weights expert-major in smem: sw[e][d], e<8 gate, e>=8 noise. 128 KB.
    extern __shared__ float sw[];
    for (int i = threadIdx.x; i < RD * RE; i += TPB) {
        int d = i >> 3, e = i & 7;           // gate_w/noise_w are [D, E] row-major
        sw[e * RD + d]       = gate_w[i];
        sw[(e + 8) * RD + d] = noise_w[i];
    }
    __syncthreads();

    const int lane  = threadIdx.x & 31;
    const int warp  = threadIdx.x >> 5;
    const int gwarp = blockIdx.x * NWARPS + warp;
    const int dsub  = lane & 7;    // d position within chunk (4 floats each)
    const int egrp  = lane >> 3;   // expert group: rows egrp*4 .. egrp*4+3

    const float* wp = sw + (egrp * 4) * RD + dsub * 4;

    for (int job = gwarp; job < TOTAL_JOBS; job += WSTRIDE) {
        const int t0 = job * 4;

        unsigned long long acc2[4][4];       // [token][expert-in-group], d-pair packed
        #pragma unroll
        for (int t = 0; t < 4; ++t)
            #pragma unroll
            for (int k = 0; k < 4; ++k) acc2[t][k] = 0ull;

        const float* xb = x + (size_t)t0 * RD + dsub * 4;

        ulonglong2 xv[4];
        #pragma unroll
        for (int t = 0; t < 4; ++t)
            xv[t] = *reinterpret_cast<const ulonglong2*>(xb + (size_t)t * RD);

        #pragma unroll 2
        for (int s = 0; s < NCHUNK; ++s) {
            // prefetch next chunk's x (wrap on last iter: dead value, valid addr)
            const int snext = (s + 1) & (NCHUNK - 1);
            ulonglong2 xn[4];
            #pragma unroll
            for (int t = 0; t < 4; ++t)
                xn[t] = *reinterpret_cast<const ulonglong2*>(
                            xb + snext * 32 + (size_t)t * RD);

            // 4 conflict-free LDS.128: this lane's 4 experts at its 4 d
            ulonglong2 wv[4];
            const float* wps = wp + s * 32;
            #pragma unroll
            for (int k = 0; k < 4; ++k)
                wv[k] = *reinterpret_cast<const ulonglong2*>(wps + k * RD);

            #pragma unroll
            for (int t = 0; t < 4; ++t)
                #pragma unroll
                for (int k = 0; k < 4; ++k) {
                    ffma2(acc2[t][k], xv[t].x, wv[k].x);
                    ffma2(acc2[t][k], xv[t].y, wv[k].y);
                }

            #pragma unroll
            for (int t = 0; t < 4; ++t) xv[t] = xn[t];
        }

        // collapse d-pair halves
        float accf[4][4];
        #pragma unroll
        for (int t = 0; t < 4; ++t)
            #pragma unroll
            for (int k = 0; k < 4; ++k)
                accf[t][k] = lo32(acc2[t][k]) + hi32(acc2[t][k]);

        // reduce over dsub (lane bits 0..2)
        #pragma unroll
        for (int m = 1; m <= 4; m <<= 1)
            #pragma unroll
            for (int t = 0; t < 4; ++t)
                #pragma unroll
                for (int k = 0; k < 4; ++k)
                    accf[t][k] += __shfl_xor_sync(0xffffffffu, accf[t][k], m);

        // gather 16 experts to lanes 0..3 (lane t finalizes token t0+t)
        float my[16];
        #pragma unroll
        for (int t = 0; t < 4; ++t)
            #pragma unroll
            for (int g = 0; g < 4; ++g)
                #pragma unroll
                for (int k = 0; k < 4; ++k) {
                    float v = __shfl_sync(0xffffffffu, accf[t][k], g * 8);
                    if (lane == t) my[g * 4 + k] = v;
                }

        if (lane < 4) {
            const int tok = t0 + lane;
            float noisy[8];
            #pragma unroll
            for (int e = 0; e < 8; ++e) {
                float lg = my[e]     + gate_b[e];
                float z  = my[e + 8] + noise_b[e];
                float sp = fmaxf(z, 0.f) + log1pf(expf(-fabsf(z)));   // softplus
                noisy[e] = lg + noise[(size_t)tok * 8 + e] * sp;
            }

            // top-2, tie-break toward lower index (matches lax.top_k)
            float v0 = -INFINITY, v1 = -INFINITY;
            int   i0 = 0,         i1 = 0;
            #pragma unroll
            for (int e = 0; e < 8; ++e) {
                float v = noisy[e];
                if (v > v0)      { v1 = v0; i1 = i0; v0 = v; i0 = e; }
                else if (v > v1) { v1 = v;  i1 = e; }
            }

            float e1  = expf(v1 - v0);
            float inv = 1.f / (1.f + e1);
            float p0 = inv, p1 = e1 * inv;

            float pv[8];
            #pragma unroll
            for (int e = 0; e < 8; ++e)
                pv[e] = (e == i0) ? p0 : ((e == i1) ? p1 : 0.f);

            float4* po = reinterpret_cast<float4*>(out + (size_t)tok * 8);
            po[0] = make_float4(pv[0], pv[1], pv[2], pv[3]);
            po[1] = make_float4(pv[4], pv[5], pv[6], pv[7]);

            const int ib = PROBS_ELEMS + tok * 2;
            if (ib + 1 < out_size) {
                out[ib]     = (float)i0;
                out[ib + 1] = (float)i1;
            }
        }
    }
}

extern "C" void kernel_launch(void* const* d_in, const int* in_sizes, int n_in,
                              void* d_out, int out_size) {
    const float* x       = (const float*)d_in[0];
    const float* gate_w  = (const float*)d_in[1];
    const float* gate_b  = (const float*)d_in[2];
    const float* noise_w = (const float*)d_in[3];
    const float* noise_b = (const float*)d_in[4];
    const float* noise   = (const float*)d_in[5];
    // d_in[6] = top_k (fixed = 2, baked in)

    const size_t smem = (size_t)RNE * RD * sizeof(float);   // 128 KB
    cudaFuncSetAttribute(router_kernel,
                         cudaFuncAttributeMaxDynamicSharedMemorySize, (int)smem);
    router_kernel<<<NBLK, TPB, smem>>>(x, gate_w, gate_b, noise_w, noise_b,
                                       noise, (float*)d_out, out_size);
}